// round 1
// baseline (speedup 1.0000x reference)
#include <cuda_runtime.h>
#include <math.h>

#define BATCH 32
#define SEQ   2048
#define DIM   1024
#define UNITS 1024

#define MT 64
#define NT 64
#define KT 32

// Scratch (no device allocs allowed)
__device__ float g_qb[BATCH * UNITS];       // query@W2 + b2 + b1
__device__ float g_scores[BATCH * SEQ];     // pre-softmax scores
__device__ float g_weights[BATCH * SEQ];    // softmax weights

// ---------------------------------------------------------------------------
// Kernel 1: g_qb[b][u] = query[b,:] @ W2[:,u] + b2[u] + b1[u]
// ---------------------------------------------------------------------------
__global__ __launch_bounds__(256) void qproj_kernel(
    const float* __restrict__ query,
    const float* __restrict__ W2,
    const float* __restrict__ b1,
    const float* __restrict__ b2)
{
    __shared__ float qrow[DIM];
    const int b = blockIdx.x;
    for (int i = threadIdx.x; i < DIM; i += blockDim.x)
        qrow[i] = query[b * DIM + i];
    __syncthreads();

    for (int u = threadIdx.x; u < UNITS; u += blockDim.x) {
        float acc = 0.f;
        #pragma unroll 8
        for (int d = 0; d < DIM; d++)
            acc = fmaf(qrow[d], W2[d * UNITS + u], acc);
        g_qb[b * UNITS + u] = acc + b1[u] + b2[u];
    }
}

// ---------------------------------------------------------------------------
// Kernel 2: fused score GEMM
//   score[m] = sum_u tanh( values[m,:] @ W1[:,u] + g_qb[b,u] ) * V[u]
// 64x64x32 smem tile, 256 threads, 4x4 register micro-tile per thread.
// Each block owns 64 rows (all within one batch since 2048 % 64 == 0) and
// loops over all 16 n-chunks, accumulating the tanh*V reduction in registers.
// ---------------------------------------------------------------------------
__global__ __launch_bounds__(256) void score_kernel(
    const float* __restrict__ values,
    const float* __restrict__ W1,
    const float* __restrict__ V)
{
    __shared__ float As[MT][33];   // values tile [row][k], pad for banks
    __shared__ float Bs[KT][68];   // W1 tile [k][n], pad 68 -> 16B-aligned rows

    const int m0  = blockIdx.x * MT;
    const int b   = m0 / SEQ;
    const int tid = threadIdx.x;
    const int tx  = tid & 15;      // n-direction (16 threads * 4 cols)
    const int ty  = tid >> 4;      // m-direction (16 threads * 4 rows)

    float p[4] = {0.f, 0.f, 0.f, 0.f};   // per-thread partial score per row

    for (int nb = 0; nb < UNITS / NT; nb++) {
        const int n0 = nb * NT;

        float acc[4][4];
        #pragma unroll
        for (int i = 0; i < 4; i++)
            #pragma unroll
            for (int j = 0; j < 4; j++)
                acc[i][j] = 0.f;

        for (int kt = 0; kt < DIM / KT; kt++) {
            const int k0 = kt * KT;

            // load values tile: 64x32 (coalesced, 8 elems/thread)
            #pragma unroll
            for (int t = 0; t < 8; t++) {
                int idx = tid + t * 256;
                int r = idx >> 5, c = idx & 31;
                As[r][c] = values[(size_t)(m0 + r) * DIM + k0 + c];
            }
            // load W1 tile: 32x64 (coalesced)
            #pragma unroll
            for (int t = 0; t < 8; t++) {
                int idx = tid + t * 256;
                int r = idx >> 6, c = idx & 63;
                Bs[r][c] = W1[(size_t)(k0 + r) * UNITS + n0 + c];
            }
            __syncthreads();

            #pragma unroll
            for (int kk = 0; kk < KT; kk++) {
                float a0 = As[ty * 4 + 0][kk];
                float a1 = As[ty * 4 + 1][kk];
                float a2 = As[ty * 4 + 2][kk];
                float a3 = As[ty * 4 + 3][kk];
                float4 bv = *(const float4*)&Bs[kk][tx * 4];
                acc[0][0] = fmaf(a0, bv.x, acc[0][0]);
                acc[0][1] = fmaf(a0, bv.y, acc[0][1]);
                acc[0][2] = fmaf(a0, bv.z, acc[0][2]);
                acc[0][3] = fmaf(a0, bv.w, acc[0][3]);
                acc[1][0] = fmaf(a1, bv.x, acc[1][0]);
                acc[1][1] = fmaf(a1, bv.y, acc[1][1]);
                acc[1][2] = fmaf(a1, bv.z, acc[1][2]);
                acc[1][3] = fmaf(a1, bv.w, acc[1][3]);
                acc[2][0] = fmaf(a2, bv.x, acc[2][0]);
                acc[2][1] = fmaf(a2, bv.y, acc[2][1]);
                acc[2][2] = fmaf(a2, bv.z, acc[2][2]);
                acc[2][3] = fmaf(a2, bv.w, acc[2][3]);
                acc[3][0] = fmaf(a3, bv.x, acc[3][0]);
                acc[3][1] = fmaf(a3, bv.y, acc[3][1]);
                acc[3][2] = fmaf(a3, bv.z, acc[3][2]);
                acc[3][3] = fmaf(a3, bv.w, acc[3][3]);
            }
            __syncthreads();
        }

        // epilogue: tanh(acc + qb) * V, reduced over the 4 local n columns
        #pragma unroll
        for (int j = 0; j < 4; j++) {
            const int n = n0 + tx * 4 + j;
            const float vj = V[n];
            const float qv = g_qb[b * UNITS + n];
            #pragma unroll
            for (int i = 0; i < 4; i++) {
                float x = acc[i][j] + qv;
                // tanh(x) = 1 - 2/(exp(2x)+1); safe at +-inf
                float e = __expf(2.f * x);
                float t = 1.f - 2.f / (e + 1.f);
                p[i] = fmaf(t, vj, p[i]);
            }
        }
    }

    // reduce partial scores across the 16 tx lanes (width-16 groups)
    #pragma unroll
    for (int i = 0; i < 4; i++) {
        #pragma unroll
        for (int off = 8; off > 0; off >>= 1)
            p[i] += __shfl_down_sync(0xffffffffu, p[i], off, 16);
    }
    if (tx == 0) {
        #pragma unroll
        for (int i = 0; i < 4; i++)
            g_scores[m0 + ty * 4 + i] = p[i];
    }
}

// ---------------------------------------------------------------------------
// Kernel 3: softmax over the sequence axis, per batch row.
// Writes g_weights, and optionally the attention_weights output region.
// ---------------------------------------------------------------------------
__global__ __launch_bounds__(256) void softmax_kernel(float* __restrict__ w_out)
{
    const int b   = blockIdx.x;
    const int tid = threadIdx.x;
    const float* sc = g_scores + b * SEQ;
    __shared__ float sred[8];

    // max
    float m = -1e30f;
    for (int i = tid; i < SEQ; i += 256) m = fmaxf(m, sc[i]);
    #pragma unroll
    for (int off = 16; off > 0; off >>= 1)
        m = fmaxf(m, __shfl_xor_sync(0xffffffffu, m, off));
    if ((tid & 31) == 0) sred[tid >> 5] = m;
    __syncthreads();
    if (tid == 0) {
        float mm = sred[0];
        #pragma unroll
        for (int i = 1; i < 8; i++) mm = fmaxf(mm, sred[i]);
        sred[0] = mm;
    }
    __syncthreads();
    const float bm = sred[0];
    __syncthreads();

    // exp + sum
    float sum = 0.f;
    for (int i = tid; i < SEQ; i += 256) {
        float e = __expf(sc[i] - bm);
        g_weights[b * SEQ + i] = e;
        sum += e;
    }
    #pragma unroll
    for (int off = 16; off > 0; off >>= 1)
        sum += __shfl_xor_sync(0xffffffffu, sum, off);
    if ((tid & 31) == 0) sred[tid >> 5] = sum;
    __syncthreads();
    if (tid == 0) {
        float s = 0.f;
        #pragma unroll
        for (int i = 0; i < 8; i++) s += sred[i];
        sred[0] = s;
    }
    __syncthreads();
    const float inv = 1.f / sred[0];

    for (int i = tid; i < SEQ; i += 256) {
        float w = g_weights[b * SEQ + i] * inv;
        g_weights[b * SEQ + i] = w;
        if (w_out) w_out[b * SEQ + i] = w;
    }
}

// ---------------------------------------------------------------------------
// Kernel 4: context[b,d] = sum_s g_weights[b,s] * values[b,s,d]
// ---------------------------------------------------------------------------
__global__ __launch_bounds__(256) void context_kernel(
    const float* __restrict__ values,
    float* __restrict__ ctx_out)
{
    const int b = blockIdx.x;
    const int c = blockIdx.y * 256 + threadIdx.x;
    const float* vp = values + (size_t)b * SEQ * DIM + c;
    const float* wp = g_weights + b * SEQ;

    float acc = 0.f;
    #pragma unroll 8
    for (int s = 0; s < SEQ; s++)
        acc = fmaf(wp[s], vp[(size_t)s * DIM], acc);

    ctx_out[b * DIM + c] = acc;
}

// ---------------------------------------------------------------------------
// Launch
// inputs (metadata order): query, values, W1, b1, W2, b2, V, bV
// output: context_vector [32,1024] then attention_weights [32,2048,1] (flat)
// ---------------------------------------------------------------------------
extern "C" void kernel_launch(void* const* d_in, const int* in_sizes, int n_in,
                              void* d_out, int out_size)
{
    const float* query  = (const float*)d_in[0];
    const float* values = (const float*)d_in[1];
    const float* W1     = (const float*)d_in[2];
    const float* b1     = (const float*)d_in[3];
    const float* W2     = (const float*)d_in[4];
    const float* b2     = (const float*)d_in[5];
    const float* V      = (const float*)d_in[6];
    // bV (d_in[7]) shifts every score equally -> softmax-invariant; unused.

    float* out = (float*)d_out;
    float* ctx_out = nullptr;
    float* w_out   = nullptr;
    if (out_size >= BATCH * DIM + BATCH * SEQ) {        // 98304: both outputs
        ctx_out = out;
        w_out   = out + BATCH * DIM;
    } else if (out_size == BATCH * SEQ) {               // 65536: weights only
        w_out = out;
    } else {                                            // 32768: context only
        ctx_out = out;
    }

    qproj_kernel<<<BATCH, 256>>>(query, W2, b1, b2);
    score_kernel<<<(BATCH * SEQ) / MT, 256>>>(values, W1, V);
    softmax_kernel<<<BATCH, 256>>>(w_out);
    if (ctx_out)
        context_kernel<<<dim3(BATCH, DIM / 256), 256>>>(values, ctx_out);
}

// round 3
// speedup vs baseline: 3.4752x; 3.4752x over previous
#include <cuda_runtime.h>
#include <stdint.h>
#include <math.h>

#define BATCH 32
#define SEQ   2048
#define DIM   1024
#define UNITS 1024

// ---------------------------------------------------------------------------
// Scratch (no device allocs allowed)
// ---------------------------------------------------------------------------
__device__ float g_qb[BATCH * UNITS];           // query@W2 + b2 + b1
__device__ float g_scores[BATCH * SEQ];
__device__ float g_weights[BATCH * SEQ];
__device__ float g_ctx_part[8][BATCH * DIM];    // split-S partials

// ---------------------------------------------------------------------------
// cp.async helpers (baseline PTX, sm_80+)
// ---------------------------------------------------------------------------
__device__ __forceinline__ uint32_t smem_u32(const void* p) {
    uint32_t a;
    asm("{ .reg .u64 t; cvta.to.shared.u64 t, %1; cvt.u32.u64 %0, t; }" : "=r"(a) : "l"(p));
    return a;
}
#define CP_ASYNC16(s, g) \
    asm volatile("cp.async.cg.shared.global [%0], [%1], 16;" :: "r"(s), "l"(g))
#define CP_COMMIT() asm volatile("cp.async.commit_group;" ::: "memory")
#define CP_WAIT1()  asm volatile("cp.async.wait_group 1;" ::: "memory")
#define CP_WAIT0()  asm volatile("cp.async.wait_group 0;" ::: "memory")

// mma.sync m16n8k8 tf32 (baseline PTX, accepted by compute_103)
__device__ __forceinline__ void mma_tf32(float* d, const uint32_t* a, const uint32_t* b) {
    asm volatile(
        "mma.sync.aligned.m16n8k8.row.col.f32.tf32.tf32.f32 "
        "{%0,%1,%2,%3}, {%4,%5,%6,%7}, {%8,%9}, {%0,%1,%2,%3};"
        : "+f"(d[0]), "+f"(d[1]), "+f"(d[2]), "+f"(d[3])
        : "r"(a[0]), "r"(a[1]), "r"(a[2]), "r"(a[3]), "r"(b[0]), "r"(b[1]));
}

// ---------------------------------------------------------------------------
// FMA-only tanh (no MUFU): abs err < ~5e-5
// ---------------------------------------------------------------------------
__device__ __forceinline__ float tanh_fast(float x) {
    float ax = fminf(fabsf(x), 10.0f);
    float t  = ax * 2.885390081777927f;                  // 2*|x|*log2(e)
    float fn = t + 12582912.0f;                          // round-to-nearest magic
    int   n  = __float_as_int(fn) - __float_as_int(12582912.0f);
    float f  = t - (fn - 12582912.0f);                   // f in [-0.5, 0.5]
    float p  = 9.6181e-3f;
    p = fmaf(p, f, 5.5504e-2f);
    p = fmaf(p, f, 2.4022651e-1f);
    p = fmaf(p, f, 6.9314718e-1f);
    p = fmaf(p, f, 1.0f);
    float e = __int_as_float(__float_as_int(p) + (n << 23));   // exp(2|x|)
    float d = e + 1.0f;
    float r = __int_as_float(0x7EF311C3u - __float_as_int(d)); // ~1/d seed
    r = r * fmaf(-d, r, 2.0f);
    r = r * fmaf(-d, r, 2.0f);
    float th = fmaf(-2.0f, r, 1.0f);                     // tanh(|x|) >= 0
    return __int_as_float(__float_as_int(th) | (__float_as_int(x) & 0x80000000));
}

// ---------------------------------------------------------------------------
// Kernel 1: g_qb[b][u] = query[b,:] @ W2[:,u] + b2[u] + b1[u]
// ---------------------------------------------------------------------------
__global__ __launch_bounds__(256) void qproj_kernel(
    const float* __restrict__ query, const float* __restrict__ W2,
    const float* __restrict__ b1, const float* __restrict__ b2)
{
    __shared__ float qrow[DIM];
    const int b = blockIdx.x;
    for (int i = threadIdx.x; i < DIM; i += blockDim.x)
        qrow[i] = query[b * DIM + i];
    __syncthreads();
    for (int u = threadIdx.x; u < UNITS; u += blockDim.x) {
        float acc = 0.f;
        #pragma unroll 8
        for (int d = 0; d < DIM; d++)
            acc = fmaf(qrow[d], W2[d * UNITS + u], acc);
        g_qb[b * UNITS + u] = acc + b1[u] + b2[u];
    }
}

// ---------------------------------------------------------------------------
// Kernel 2: fused score GEMM via mma.sync tf32
//   scores[m] = sum_u tanh( values[m,:]@W1[:,u] + qb[b,u] ) * V[u]
// CTA: M=128, N=256 per nb pass (4 passes), K chunks of 32, double-buffered
// cp.async. 8 warps: 2(M) x 4(N); warp tile 64x64 = 4 x 8 m16n8k8 tiles.
// ---------------------------------------------------------------------------
// Shared layout (floats):
#define A_PITCH 36
#define B_PITCH 264
#define OFF_A0   0
#define OFF_A1   (128 * A_PITCH)            // 4608
#define OFF_B0   (2 * 128 * A_PITCH)        // 9216
#define OFF_B1   (OFF_B0 + 32 * B_PITCH)    // 17664
#define OFF_QB   (OFF_B0 + 2 * 32 * B_PITCH)  // 26112
#define OFF_V    (OFF_QB + 256)
#define OFF_SC   (OFF_V + 256)
#define SMEM_FLOATS (OFF_SC + 128)
#define SMEM_SCORE_BYTES (SMEM_FLOATS * 4)  // 107520-ish

__device__ __forceinline__ void load_chunk(float* sm, int buf,
                                           const float* __restrict__ values,
                                           const float* __restrict__ W1,
                                           int m0, int n0, int k0, int tid)
{
    const uint32_t a_s = smem_u32(sm + (buf ? OFF_A1 : OFF_A0));
    const uint32_t b_s = smem_u32(sm + (buf ? OFF_B1 : OFF_B0));
    // A: values tile 128 x 32 (1024 16B-chunks)
    #pragma unroll
    for (int t = 0; t < 4; t++) {
        int idx = tid + t * 256;
        int r = idx >> 3, c = idx & 7;
        CP_ASYNC16(a_s + (r * A_PITCH + c * 4) * 4,
                   values + (size_t)(m0 + r) * DIM + k0 + c * 4);
    }
    // B: W1 tile 32 x 256 (2048 16B-chunks), K-major direct
    #pragma unroll
    for (int t = 0; t < 8; t++) {
        int idx = tid + t * 256;
        int r = idx >> 6, c = idx & 63;
        CP_ASYNC16(b_s + (r * B_PITCH + c * 4) * 4,
                   W1 + (size_t)(k0 + r) * UNITS + n0 + c * 4);
    }
}

__global__ __launch_bounds__(256, 1) void score_kernel(
    const float* __restrict__ values, const float* __restrict__ W1,
    const float* __restrict__ V)
{
    extern __shared__ float sm[];
    const int tid  = threadIdx.x;
    const int warp = tid >> 5;
    const int lane = tid & 31;
    const int wm   = warp >> 2;          // 0..1
    const int wn   = warp & 3;           // 0..3
    const int grp  = lane >> 2;          // 0..7
    const int ctg  = lane & 3;           // 0..3
    const int m0   = blockIdx.x * 128;
    const int b    = m0 >> 11;

    float* s_qb = sm + OFF_QB;
    float* s_V  = sm + OFF_V;
    float* s_sc = sm + OFF_SC;
    if (tid < 128) s_sc[tid] = 0.f;

    float p[4][2];
    #pragma unroll
    for (int i = 0; i < 4; i++) { p[i][0] = 0.f; p[i][1] = 0.f; }

    for (int nb = 0; nb < 4; nb++) {
        const int n0 = nb * 256;
        if (tid < 256) {                  // all threads
            s_qb[tid] = g_qb[b * UNITS + n0 + tid];
            s_V[tid]  = V[n0 + tid];
        }

        float acc[4][8][4];
        #pragma unroll
        for (int mi = 0; mi < 4; mi++)
            #pragma unroll
            for (int ni = 0; ni < 8; ni++)
                #pragma unroll
                for (int r = 0; r < 4; r++)
                    acc[mi][ni][r] = 0.f;

        load_chunk(sm, 0, values, W1, m0, n0, 0, tid);
        CP_COMMIT();

        for (int kt = 0; kt < 32; kt++) {
            const int buf = kt & 1;
            if (kt < 31) {
                load_chunk(sm, buf ^ 1, values, W1, m0, n0, (kt + 1) * 32, tid);
                CP_COMMIT();
                CP_WAIT1();
            } else {
                CP_WAIT0();
            }
            __syncthreads();

            const float* Ab = sm + (buf ? OFF_A1 : OFF_A0);
            const float* Bb = sm + (buf ? OFF_B1 : OFF_B0);

            #pragma unroll
            for (int k8 = 0; k8 < 4; k8++) {
                const int ka = k8 * 8 + ctg;
                uint32_t afr[4][4], bfr[8][2];
                #pragma unroll
                for (int mi = 0; mi < 4; mi++) {
                    const int r = wm * 64 + mi * 16 + grp;
                    afr[mi][0] = __float_as_uint(Ab[r * A_PITCH + ka]);
                    afr[mi][1] = __float_as_uint(Ab[(r + 8) * A_PITCH + ka]);
                    afr[mi][2] = __float_as_uint(Ab[r * A_PITCH + ka + 4]);
                    afr[mi][3] = __float_as_uint(Ab[(r + 8) * A_PITCH + ka + 4]);
                }
                #pragma unroll
                for (int ni = 0; ni < 8; ni++) {
                    const int cn = wn * 64 + ni * 8 + grp;
                    bfr[ni][0] = __float_as_uint(Bb[ka * B_PITCH + cn]);
                    bfr[ni][1] = __float_as_uint(Bb[(ka + 4) * B_PITCH + cn]);
                }
                #pragma unroll
                for (int mi = 0; mi < 4; mi++)
                    #pragma unroll
                    for (int ni = 0; ni < 8; ni++)
                        mma_tf32(acc[mi][ni], afr[mi], bfr[ni]);
            }
            __syncthreads();
        }

        // epilogue: tanh(acc + qb) * V  -> per-row partials
        #pragma unroll
        for (int mi = 0; mi < 4; mi++) {
            #pragma unroll
            for (int ni = 0; ni < 8; ni++) {
                const int nloc = wn * 64 + ni * 8 + ctg * 2;
                const float q0 = s_qb[nloc],     v0 = s_V[nloc];
                const float q1 = s_qb[nloc + 1], v1 = s_V[nloc + 1];
                p[mi][0] = fmaf(tanh_fast(acc[mi][ni][0] + q0), v0, p[mi][0]);
                p[mi][0] = fmaf(tanh_fast(acc[mi][ni][1] + q1), v1, p[mi][0]);
                p[mi][1] = fmaf(tanh_fast(acc[mi][ni][2] + q0), v0, p[mi][1]);
                p[mi][1] = fmaf(tanh_fast(acc[mi][ni][3] + q1), v1, p[mi][1]);
            }
        }
        __syncthreads();   // s_qb/s_V reads done before next nb overwrites
    }

    // reduce across quad lanes (same row, different ctg), then across n-warps
    #pragma unroll
    for (int mi = 0; mi < 4; mi++) {
        #pragma unroll
        for (int r = 0; r < 2; r++) {
            float v = p[mi][r];
            v += __shfl_xor_sync(0xffffffffu, v, 1);
            v += __shfl_xor_sync(0xffffffffu, v, 2);
            if (ctg == 0)
                atomicAdd(&s_sc[wm * 64 + mi * 16 + r * 8 + grp], v);
        }
    }
    __syncthreads();
    if (tid < 128) g_scores[m0 + tid] = s_sc[tid];
}

// ---------------------------------------------------------------------------
// Kernel 3: softmax over sequence axis
// ---------------------------------------------------------------------------
__global__ __launch_bounds__(256) void softmax_kernel(float* __restrict__ w_out)
{
    const int b   = blockIdx.x;
    const int tid = threadIdx.x;
    const float* sc = g_scores + b * SEQ;
    __shared__ float sred[8];

    float m = -1e30f;
    for (int i = tid; i < SEQ; i += 256) m = fmaxf(m, sc[i]);
    #pragma unroll
    for (int off = 16; off > 0; off >>= 1)
        m = fmaxf(m, __shfl_xor_sync(0xffffffffu, m, off));
    if ((tid & 31) == 0) sred[tid >> 5] = m;
    __syncthreads();
    if (tid == 0) {
        float mm = sred[0];
        #pragma unroll
        for (int i = 1; i < 8; i++) mm = fmaxf(mm, sred[i]);
        sred[0] = mm;
    }
    __syncthreads();
    const float bm = sred[0];
    __syncthreads();

    float sum = 0.f;
    for (int i = tid; i < SEQ; i += 256) {
        float e = __expf(sc[i] - bm);
        g_weights[b * SEQ + i] = e;
        sum += e;
    }
    #pragma unroll
    for (int off = 16; off > 0; off >>= 1)
        sum += __shfl_xor_sync(0xffffffffu, sum, off);
    if ((tid & 31) == 0) sred[tid >> 5] = sum;
    __syncthreads();
    if (tid == 0) {
        float s = 0.f;
        #pragma unroll
        for (int i = 0; i < 8; i++) s += sred[i];
        sred[0] = s;
    }
    __syncthreads();
    const float inv = 1.f / sred[0];

    for (int i = tid; i < SEQ; i += 256) {
        float w = g_weights[b * SEQ + i] * inv;
        g_weights[b * SEQ + i] = w;
        if (w_out) w_out[b * SEQ + i] = w;
    }
}

// ---------------------------------------------------------------------------
// Kernel 4a: context partials (split-S by 8)
// ---------------------------------------------------------------------------
__global__ __launch_bounds__(256) void ctx_part_kernel(const float* __restrict__ values)
{
    const int b  = blockIdx.x;
    const int sp = blockIdx.y;
    const int d4 = threadIdx.x;
    const float4* vp = (const float4*)(values + (size_t)b * SEQ * DIM);
    const float*  wp = g_weights + b * SEQ;

    float4 acc = make_float4(0.f, 0.f, 0.f, 0.f);
    const int s0 = sp * 256;
    #pragma unroll 1
    for (int s = s0; s < s0 + 256; s += 4) {
        float w0 = wp[s], w1 = wp[s + 1], w2 = wp[s + 2], w3 = wp[s + 3];
        float4 v0 = vp[(size_t)(s)     * 256 + d4];
        float4 v1 = vp[(size_t)(s + 1) * 256 + d4];
        float4 v2 = vp[(size_t)(s + 2) * 256 + d4];
        float4 v3 = vp[(size_t)(s + 3) * 256 + d4];
        acc.x = fmaf(w0, v0.x, fmaf(w1, v1.x, fmaf(w2, v2.x, fmaf(w3, v3.x, acc.x))));
        acc.y = fmaf(w0, v0.y, fmaf(w1, v1.y, fmaf(w2, v2.y, fmaf(w3, v3.y, acc.y))));
        acc.z = fmaf(w0, v0.z, fmaf(w1, v1.z, fmaf(w2, v2.z, fmaf(w3, v3.z, acc.z))));
        acc.w = fmaf(w0, v0.w, fmaf(w1, v1.w, fmaf(w2, v2.w, fmaf(w3, v3.w, acc.w))));
    }
    ((float4*)&g_ctx_part[sp][b * DIM])[d4] = acc;
}

// Kernel 4b: reduce partials -> context output
__global__ __launch_bounds__(256) void ctx_reduce_kernel(float* __restrict__ ctx_out)
{
    const int i = blockIdx.x * 256 + threadIdx.x;
    float acc = 0.f;
    #pragma unroll
    for (int p = 0; p < 8; p++) acc += g_ctx_part[p][i];
    ctx_out[i] = acc;
}

// ---------------------------------------------------------------------------
// Launch: inputs = query, values, W1, b1, W2, b2, V, bV
// output = context [32,1024] then attention_weights [32,2048]
// ---------------------------------------------------------------------------
extern "C" void kernel_launch(void* const* d_in, const int* in_sizes, int n_in,
                              void* d_out, int out_size)
{
    const float* query  = (const float*)d_in[0];
    const float* values = (const float*)d_in[1];
    const float* W1     = (const float*)d_in[2];
    const float* b1     = (const float*)d_in[3];
    const float* W2     = (const float*)d_in[4];
    const float* b2     = (const float*)d_in[5];
    const float* V      = (const float*)d_in[6];
    // bV shifts every score equally -> softmax-invariant; unused.

    float* out = (float*)d_out;
    float* ctx_out = nullptr;
    float* w_out   = nullptr;
    if (out_size >= BATCH * DIM + BATCH * SEQ) {
        ctx_out = out;
        w_out   = out + BATCH * DIM;
    } else if (out_size == BATCH * SEQ) {
        w_out = out;
    } else {
        ctx_out = out;
    }

    static int smem_set = 0;
    if (!smem_set) {
        cudaFuncSetAttribute(score_kernel, cudaFuncAttributeMaxDynamicSharedMemorySize,
                             SMEM_SCORE_BYTES);
        smem_set = 1;
    }

    qproj_kernel<<<BATCH, 256>>>(query, W2, b1, b2);
    score_kernel<<<(BATCH * SEQ) / 128, 256, SMEM_SCORE_BYTES>>>(values, W1, V);
    softmax_kernel<<<BATCH, 256>>>(w_out);
    if (ctx_out) {
        ctx_part_kernel<<<dim3(BATCH, 8), 256>>>(values);
        ctx_reduce_kernel<<<(BATCH * DIM) / 256, 256>>>(ctx_out);
    }
}